// round 3
// baseline (speedup 1.0000x reference)
#include <cuda_runtime.h>

// VectorQuantizer: x[128,2048,64] f32, W[512,64] f32
// out = concat(quantized[16777216], loss[1], indices[262144]) as f32 (layout
// adapted from out_size at runtime).

#define KCODES 512
#define DIM 64
#define ROWS_PER_BLK 256
#define N_ROWS (128 * 2048)
#define N_BLKS (N_ROWS / ROWS_PER_BLK)   // 1024
#define PAD 65                            // row pitch in smem floats (conflict-free)
#define SMEM_FLOATS (KCODES * DIM + KCODES + ROWS_PER_BLK * PAD)
#define SMEM_BYTES (SMEM_FLOATS * 4)

__device__ float g_blockSums[N_BLKS];

__global__ void __launch_bounds__(256, 1) vq_main_kernel(
    const float* __restrict__ x, const float* __restrict__ W,
    float* __restrict__ qout, float* __restrict__ idx_out)
{
    extern __shared__ float sm[];
    float* sW   = sm;                       // [512][64]
    float* sWsq = sm + KCODES * DIM;        // [512]
    float* sX   = sm + KCODES * DIM + KCODES; // [256][65]
    const int tid = threadIdx.x;

    // ---- cooperative loads (coalesced float4) ----
    {
        const float4* Wg = (const float4*)W;
        float4* sW4 = (float4*)sW;
        #pragma unroll
        for (int i = tid; i < KCODES * DIM / 4; i += 256) sW4[i] = Wg[i];
    }
    {
        const float4* xg = (const float4*)(x + (size_t)blockIdx.x * (ROWS_PER_BLK * DIM));
        #pragma unroll
        for (int i = tid; i < ROWS_PER_BLK * DIM / 4; i += 256) {
            float4 v4 = xg[i];
            int el = i * 4;
            int r = el >> 6;
            int dd = el & 63;
            float* p = sX + r * PAD + dd;
            p[0] = v4.x; p[1] = v4.y; p[2] = v4.z; p[3] = v4.w;
        }
    }
    __syncthreads();

    // ---- wsq_k = sum_d W[k][d]^2, sequential round-to-nearest (match jnp.sum) ----
    for (int k = tid; k < KCODES; k += 256) {
        const float* w = sW + k * DIM;
        float s = 0.f;
        #pragma unroll
        for (int d = 0; d < DIM; d++) s = __fadd_rn(s, __fmul_rn(w[d], w[d]));
        sWsq[k] = s;
    }
    __syncthreads();

    // ---- per-row normalization (one row per thread) ----
    float v[DIM];
    {
        const float* xr = sX + tid * PAD;   // bank-conflict-free (pitch 65)
        #pragma unroll
        for (int d = 0; d < DIM; d++) v[d] = xr[d];
    }
    float sum = 0.f;
    #pragma unroll
    for (int d = 0; d < DIM; d++) sum = __fadd_rn(sum, v[d]);
    float mean = __fmul_rn(sum, 0.015625f);            // /64 exact
    float ss = 0.f;
    #pragma unroll
    for (int d = 0; d < DIM; d++) {
        float t = __fadd_rn(v[d], -mean);
        ss = __fadd_rn(ss, __fmul_rn(t, t));
    }
    float stdv  = __fsqrt_rn(__fdiv_rn(ss, 63.f));     // ddof=1
    float denom = __fadd_rn(stdv, 1e-7f);
    #pragma unroll
    for (int d = 0; d < DIM; d++)
        v[d] = __fdiv_rn(__fadd_rn(v[d], -mean), denom);   // xn
    float xsq = 0.f;
    #pragma unroll
    for (int d = 0; d < DIM; d++) xsq = __fadd_rn(xsq, __fmul_rn(v[d], v[d]));

    // ---- argmin over 512 codes, 4-wide FFMA, score = fl((xsq+wsq) - fl(2*dot)) ----
    float best = 3.402823466e38f;
    int bidx = 0;
    #pragma unroll 1
    for (int k = 0; k < KCODES; k += 4) {
        const float4* w0 = (const float4*)(sW + (k + 0) * DIM);
        const float4* w1 = (const float4*)(sW + (k + 1) * DIM);
        const float4* w2 = (const float4*)(sW + (k + 2) * DIM);
        const float4* w3 = (const float4*)(sW + (k + 3) * DIM);
        float a0 = 0.f, a1 = 0.f, a2 = 0.f, a3 = 0.f;
        #pragma unroll
        for (int q = 0; q < DIM / 4; q++) {
            float4 b0 = w0[q], b1 = w1[q], b2 = w2[q], b3 = w3[q];
            float x0 = v[4 * q + 0], x1 = v[4 * q + 1];
            float x2 = v[4 * q + 2], x3 = v[4 * q + 3];
            a0 = fmaf(x0, b0.x, a0); a0 = fmaf(x1, b0.y, a0);
            a0 = fmaf(x2, b0.z, a0); a0 = fmaf(x3, b0.w, a0);
            a1 = fmaf(x0, b1.x, a1); a1 = fmaf(x1, b1.y, a1);
            a1 = fmaf(x2, b1.z, a1); a1 = fmaf(x3, b1.w, a1);
            a2 = fmaf(x0, b2.x, a2); a2 = fmaf(x1, b2.y, a2);
            a2 = fmaf(x2, b2.z, a2); a2 = fmaf(x3, b2.w, a2);
            a3 = fmaf(x0, b3.x, a3); a3 = fmaf(x1, b3.y, a3);
            a3 = fmaf(x2, b3.z, a3); a3 = fmaf(x3, b3.w, a3);
        }
        float s0 = __fsub_rn(__fadd_rn(xsq, sWsq[k + 0]), __fmul_rn(2.f, a0));
        float s1 = __fsub_rn(__fadd_rn(xsq, sWsq[k + 1]), __fmul_rn(2.f, a1));
        float s2 = __fsub_rn(__fadd_rn(xsq, sWsq[k + 2]), __fmul_rn(2.f, a2));
        float s3 = __fsub_rn(__fadd_rn(xsq, sWsq[k + 3]), __fmul_rn(2.f, a3));
        if (s0 < best) { best = s0; bidx = k + 0; }
        if (s1 < best) { best = s1; bidx = k + 1; }
        if (s2 < best) { best = s2; bidx = k + 2; }
        if (s3 < best) { best = s3; bidx = k + 3; }
    }

    // ---- epilogue: loss partial + denormalized quantized (staged to smem) ----
    float lsum = 0.f;
    {
        const float4* wb = (const float4*)(sW + bidx * DIM);
        float* wrow = sX + tid * PAD;
        #pragma unroll
        for (int q = 0; q < DIM / 4; q++) {
            float4 b = wb[q];
            float d0 = b.x - v[4 * q + 0];
            float d1 = b.y - v[4 * q + 1];
            float d2 = b.z - v[4 * q + 2];
            float d3 = b.w - v[4 * q + 3];
            lsum = fmaf(d0, d0, lsum); lsum = fmaf(d1, d1, lsum);
            lsum = fmaf(d2, d2, lsum); lsum = fmaf(d3, d3, lsum);
            wrow[4 * q + 0] = fmaf(b.x, denom, mean);
            wrow[4 * q + 1] = fmaf(b.y, denom, mean);
            wrow[4 * q + 2] = fmaf(b.z, denom, mean);
            wrow[4 * q + 3] = fmaf(b.w, denom, mean);
        }
    }
    if (idx_out)
        idx_out[(size_t)blockIdx.x * ROWS_PER_BLK + tid] = (float)bidx;
    __syncthreads();

    // ---- coalesced quantized store ----
    {
        float* og = qout + (size_t)blockIdx.x * (ROWS_PER_BLK * DIM);
        #pragma unroll
        for (int i = tid; i < ROWS_PER_BLK * DIM; i += 256)
            og[i] = sX[(i >> 6) * PAD + (i & 63)];
    }

    // ---- deterministic block loss reduction ----
    float l = lsum;
    #pragma unroll
    for (int off = 16; off; off >>= 1)
        l = __fadd_rn(l, __shfl_down_sync(0xffffffffu, l, off));
    __shared__ float warpAcc[8];
    if ((tid & 31) == 0) warpAcc[tid >> 5] = l;
    __syncthreads();
    if (tid == 0) {
        float t = warpAcc[0];
        #pragma unroll
        for (int w = 1; w < 8; w++) t = __fadd_rn(t, warpAcc[w]);
        g_blockSums[blockIdx.x] = t;
    }
}

__global__ void vq_loss_kernel(float* __restrict__ loss_out)
{
    __shared__ float sh[256];
    int t = threadIdx.x;
    float s = 0.f;
    #pragma unroll
    for (int i = 0; i < N_BLKS / 256; i++)
        s = __fadd_rn(s, g_blockSums[t + i * 256]);
    sh[t] = s;
    __syncthreads();
    #pragma unroll
    for (int off = 128; off > 0; off >>= 1) {
        if (t < off) sh[t] = __fadd_rn(sh[t], sh[t + off]);
        __syncthreads();
    }
    if (t == 0)
        loss_out[0] = 1.25f * sh[0] * (1.0f / 16777216.0f);
}

extern "C" void kernel_launch(void* const* d_in, const int* in_sizes, int n_in,
                              void* d_out, int out_size)
{
    const float* x = (const float*)d_in[0];
    const float* W = (const float*)d_in[1];
    float* out = (float*)d_out;

    const long long q = (long long)N_ROWS * DIM;  // 16777216
    float* loss_out = nullptr;
    float* idx_out  = nullptr;
    long long osz = (long long)out_size;
    if (osz >= q + 1 + N_ROWS) { loss_out = out + q; idx_out = out + q + 1; }
    else if (osz == q + N_ROWS) { idx_out = out + q; }
    else if (osz == q + 1)      { loss_out = out + q; }

    cudaFuncSetAttribute(vq_main_kernel,
                         cudaFuncAttributeMaxDynamicSharedMemorySize, SMEM_BYTES);
    vq_main_kernel<<<N_BLKS, 256, SMEM_BYTES>>>(x, W, out, idx_out);
    if (loss_out)
        vq_loss_kernel<<<1, 256>>>(loss_out);
}

// round 8
// speedup vs baseline: 1.2363x; 1.2363x over previous
#include <cuda_runtime.h>
#include <cuda_bf16.h>
#include <cstdint>

// VectorQuantizer via warp-level mma.sync (bf16 split hi/lo, fp32 accum)
// + exact fp32 re-score of per-lane top-2 candidates (argmin fidelity).
// x[128,2048,64] f32, W[512,64] f32.
// out = concat(quantized[16777216], loss[1], indices[262144]) f32.

#define KCODES 512
#define DIM 64
#define TILE_M 128
#define N_ROWS (128 * 2048)
#define N_TILES (N_ROWS / TILE_M)   // 2048
#define THREADS 256

#define WPITCH 144                  // bytes per bf16 row (64*2 + 16 pad) -> conflict-free ldmatrix

// ---- shared memory layout (bytes) ----
#define SM_B_HI   0
#define SM_B_LO   (SM_B_HI + KCODES * WPITCH)      // 73728
#define SM_A_HI   (SM_B_LO + KCODES * WPITCH)      // 147456
#define SM_A_LO   (SM_A_HI + TILE_M * WPITCH)      // 165888
#define SM_XS     (SM_A_LO + TILE_M * WPITCH)      // 184320 : float[128][65]
#define SM_WSQ    (SM_XS + TILE_M * 65 * 4)        // 217600 : float[512]
#define SM_XSQ    (SM_WSQ + KCODES * 4)            // 219648
#define SM_MEAN   (SM_XSQ + TILE_M * 4)            // 220160
#define SM_DENOM  (SM_MEAN + TILE_M * 4)           // 220672
#define SM_IDX    (SM_DENOM + TILE_M * 4)          // 221184 : int[128]
#define SM_WACC   (SM_IDX + TILE_M * 4)            // 221696 : float[8]
#define SM_TOTAL  (SM_WACC + 128)                  // 221824 B

__device__ __nv_bfloat16 g_Whi[KCODES * DIM];
__device__ __nv_bfloat16 g_Wlo[KCODES * DIM];
__device__ float g_wsq[KCODES];
__device__ float g_blockSums[N_TILES];

__device__ __forceinline__ uint32_t smem_u32(const void* p) {
    uint32_t a;
    asm("{ .reg .u64 t; cvta.to.shared.u64 t, %1; cvt.u32.u64 %0, t; }"
        : "=r"(a) : "l"(p));
    return a;
}

#define LDSM_X4(r0, r1, r2, r3, addr) \
    asm volatile("ldmatrix.sync.aligned.m8n8.x4.shared.b16 {%0,%1,%2,%3}, [%4];" \
        : "=r"(r0), "=r"(r1), "=r"(r2), "=r"(r3) : "r"(addr))

#define MMA_BF16(c, a, b) \
    asm volatile("mma.sync.aligned.m16n8k16.row.col.f32.bf16.bf16.f32 " \
        "{%0,%1,%2,%3}, {%4,%5,%6,%7}, {%8,%9}, {%0,%1,%2,%3};" \
        : "+f"((c)[0]), "+f"((c)[1]), "+f"((c)[2]), "+f"((c)[3]) \
        : "r"((a)[0]), "r"((a)[1]), "r"((a)[2]), "r"((a)[3]), \
          "r"((b)[0]), "r"((b)[1]))

// Exact fp32 score, identical arithmetic order to the validated FFMA kernel:
// dot accumulated by sequential fmaf in ascending d; score = (xsq+wsq) - 2*dot.
__device__ __forceinline__ float exact_score(const float* __restrict__ xr,
                                             float xsq,
                                             const float* __restrict__ W,
                                             const float* __restrict__ WSQ,
                                             int k)
{
    const float4* wr = (const float4*)(W + (size_t)k * DIM);
    float a = 0.f;
    #pragma unroll
    for (int q = 0; q < DIM / 4; q++) {
        float4 b = wr[q];
        a = fmaf(xr[4 * q + 0], b.x, a);
        a = fmaf(xr[4 * q + 1], b.y, a);
        a = fmaf(xr[4 * q + 2], b.z, a);
        a = fmaf(xr[4 * q + 3], b.w, a);
    }
    return __fsub_rn(__fadd_rn(xsq, WSQ[k]), __fmul_rn(2.f, a));
}

// ---------------- prep: W -> bf16 hi/lo + wsq ----------------
__global__ void vq_prep(const float* __restrict__ W) {
    int k = blockIdx.x * 256 + threadIdx.x;
    if (k < KCODES) {
        const float* w = W + k * DIM;
        float s = 0.f;
        #pragma unroll
        for (int d = 0; d < DIM; d++) s = __fadd_rn(s, __fmul_rn(w[d], w[d]));
        g_wsq[k] = s;
        #pragma unroll
        for (int d = 0; d < DIM; d++) {
            float f = w[d];
            __nv_bfloat16 h = __float2bfloat16(f);
            float lo = __fadd_rn(f, -__bfloat162float(h));
            g_Whi[k * DIM + d] = h;
            g_Wlo[k * DIM + d] = __float2bfloat16(lo);
        }
    }
}

// ---------------- main ----------------
__global__ void __launch_bounds__(THREADS, 1) vq_main(
    const float* __restrict__ x, const float* __restrict__ W,
    float* __restrict__ qout, float* __restrict__ idx_out)
{
    extern __shared__ char smc[];
    const uint32_t smb = smem_u32(smc);
    const int tid = threadIdx.x, wid = tid >> 5, lid = tid & 31;
    float* XS   = (float*)(smc + SM_XS);
    float* WSQ  = (float*)(smc + SM_WSQ);
    float* XSQ  = (float*)(smc + SM_XSQ);
    int*   IDX  = (int*)(smc + SM_IDX);

    // ---- cooperative loads: W bf16 hi/lo (padded rows) + wsq + x tile ----
    {
        const uint4* gh = (const uint4*)g_Whi;
        const uint4* gl = (const uint4*)g_Wlo;
        #pragma unroll
        for (int i = tid; i < KCODES * 8; i += THREADS) {   // 8 x uint4 per row
            int row = i >> 3, c = i & 7;
            uint32_t off = (uint32_t)(row * WPITCH + c * 16);
            *(uint4*)(smc + SM_B_HI + off) = gh[i];
            *(uint4*)(smc + SM_B_LO + off) = gl[i];
        }
        for (int i = tid; i < KCODES; i += THREADS) WSQ[i] = g_wsq[i];
        const float4* xg = (const float4*)(x + (size_t)blockIdx.x * (TILE_M * DIM));
        #pragma unroll
        for (int i = tid; i < TILE_M * DIM / 4; i += THREADS) {
            float4 v4 = xg[i];
            int el = i * 4, r = el >> 6, dd = el & 63;
            float* p = XS + r * 65 + dd;
            p[0] = v4.x; p[1] = v4.y; p[2] = v4.z; p[3] = v4.w;
        }
    }
    __syncthreads();

    // ---- per-row normalization (exact sequential order, 1 thread/row) ----
    if (tid < TILE_M) {
        float v[DIM];
        float* xr = XS + tid * 65;
        #pragma unroll
        for (int d = 0; d < DIM; d++) v[d] = xr[d];
        float sum = 0.f;
        #pragma unroll
        for (int d = 0; d < DIM; d++) sum = __fadd_rn(sum, v[d]);
        float mean = __fmul_rn(sum, 0.015625f);
        float ss = 0.f;
        #pragma unroll
        for (int d = 0; d < DIM; d++) {
            float t = __fadd_rn(v[d], -mean);
            ss = __fadd_rn(ss, __fmul_rn(t, t));
        }
        float stdv  = __fsqrt_rn(__fdiv_rn(ss, 63.f));
        float denom = __fadd_rn(stdv, 1e-7f);
        float xsq = 0.f;
        #pragma unroll
        for (int d = 0; d < DIM; d++) {
            v[d] = __fdiv_rn(__fadd_rn(v[d], -mean), denom);
            xsq = __fadd_rn(xsq, __fmul_rn(v[d], v[d]));
            xr[d] = v[d];                       // keep exact xn for loss/rescore
        }
        // split to bf16 hi/lo, store padded rows for ldmatrix
        uint32_t base = (uint32_t)tid * WPITCH;
        #pragma unroll
        for (int q = 0; q < 8; q++) {
            uint32_t pkh[4], pkl[4];
            #pragma unroll
            for (int m = 0; m < 4; m++) {
                float a = v[q * 8 + 2 * m], b = v[q * 8 + 2 * m + 1];
                __nv_bfloat16 ha = __float2bfloat16(a), hb = __float2bfloat16(b);
                float la = __fadd_rn(a, -__bfloat162float(ha));
                float lb = __fadd_rn(b, -__bfloat162float(hb));
                __nv_bfloat162 h2 = __halves2bfloat162(ha, hb);
                __nv_bfloat162 l2 = __halves2bfloat162(__float2bfloat16(la),
                                                       __float2bfloat16(lb));
                pkh[m] = *(uint32_t*)&h2;
                pkl[m] = *(uint32_t*)&l2;
            }
            uint32_t off = base + q * 16;
            *(uint4*)(smc + SM_A_HI + off) = make_uint4(pkh[0], pkh[1], pkh[2], pkh[3]);
            *(uint4*)(smc + SM_A_LO + off) = make_uint4(pkl[0], pkl[1], pkl[2], pkl[3]);
        }
        XSQ[tid] = xsq;
        ((float*)(smc + SM_MEAN))[tid]  = mean;
        ((float*)(smc + SM_DENOM))[tid] = denom;
    }
    __syncthreads();

    // ---- warp MMA: C[128,512] = Xhi*Whi^T + Xhi*Wlo^T + Xlo*Whi^T ----
    {
        const int g = lid >> 2, t = lid & 3;
        const int row0 = wid * 16 + g, row1 = row0 + 8;
        const float xsq0 = XSQ[row0], xsq1 = XSQ[row1];

        // A fragment addresses (lane-mapped for ldmatrix.x4)
        const uint32_t aRow  = (uint32_t)(wid * 16 + ((lid & 8) ? 8 : 0) + (lid & 7));
        const uint32_t aKoff = (lid & 16) ? 16u : 0u;
        const uint32_t aHiA = smb + SM_A_HI + aRow * WPITCH + aKoff;
        const uint32_t aLoA = smb + SM_A_LO + aRow * WPITCH + aKoff;

        uint32_t Ah[4][4], Al[4][4];
        #pragma unroll
        for (int kc = 0; kc < 4; kc++) {
            LDSM_X4(Ah[kc][0], Ah[kc][1], Ah[kc][2], Ah[kc][3], aHiA + kc * 32);
            LDSM_X4(Al[kc][0], Al[kc][1], Al[kc][2], Al[kc][3], aLoA + kc * 32);
        }

        // B fragment lane mapping
        const uint32_t bRsel = ((lid & 16) ? 8u : 0u) + (uint32_t)(lid & 7);
        const uint32_t bKoff = (lid & 8) ? 16u : 0u;

        // per-lane top-2 (mma scores) for each of the 2 rows
        float b1r0 = 3.402823466e38f, b2r0 = 3.402823466e38f;
        float b1r1 = 3.402823466e38f, b2r1 = 3.402823466e38f;
        int i1r0 = 0, i2r0 = 0, i1r1 = 0, i2r1 = 0;

        #pragma unroll 1
        for (int nc = 0; nc < 8; nc++) {
            float acc[8][4];
            #pragma unroll
            for (int i = 0; i < 8; i++) {
                acc[i][0] = 0.f; acc[i][1] = 0.f; acc[i][2] = 0.f; acc[i][3] = 0.f;
            }
            #pragma unroll
            for (int kc = 0; kc < 4; kc++) {
                uint32_t bh[8][2], bl[8][2];
                #pragma unroll
                for (int p = 0; p < 4; p++) {
                    uint32_t nrow = (uint32_t)(nc * 64 + p * 16) + bRsel;
                    uint32_t boff = nrow * WPITCH + (uint32_t)kc * 32 + bKoff;
                    LDSM_X4(bh[2 * p][0], bh[2 * p][1], bh[2 * p + 1][0], bh[2 * p + 1][1],
                            smb + SM_B_HI + boff);
                    LDSM_X4(bl[2 * p][0], bl[2 * p][1], bl[2 * p + 1][0], bl[2 * p + 1][1],
                            smb + SM_B_LO + boff);
                }
                #pragma unroll
                for (int nt = 0; nt < 8; nt++) {
                    MMA_BF16(acc[nt], Ah[kc], bh[nt]);
                    MMA_BF16(acc[nt], Ah[kc], bl[nt]);
                    MMA_BF16(acc[nt], Al[kc], bh[nt]);
                }
            }
            // scores + top-2 tracking (ascending column order, strict <)
            #pragma unroll
            for (int nt = 0; nt < 8; nt++) {
                int cb = nc * 64 + nt * 8 + 2 * t;
                float w0 = WSQ[cb], w1 = WSQ[cb + 1];
                float s;
                s = __fsub_rn(__fadd_rn(xsq0, w0), __fmul_rn(2.f, acc[nt][0]));
                if (s < b1r0) { b2r0 = b1r0; i2r0 = i1r0; b1r0 = s; i1r0 = cb; }
                else if (s < b2r0) { b2r0 = s; i2r0 = cb; }
                s = __fsub_rn(__fadd_rn(xsq0, w1), __fmul_rn(2.f, acc[nt][1]));
                if (s < b1r0) { b2r0 = b1r0; i2r0 = i1r0; b1r0 = s; i1r0 = cb + 1; }
                else if (s < b2r0) { b2r0 = s; i2r0 = cb + 1; }
                s = __fsub_rn(__fadd_rn(xsq1, w0), __fmul_rn(2.f, acc[nt][2]));
                if (s < b1r1) { b2r1 = b1r1; i2r1 = i1r1; b1r1 = s; i1r1 = cb; }
                else if (s < b2r1) { b2r1 = s; i2r1 = cb; }
                s = __fsub_rn(__fadd_rn(xsq1, w1), __fmul_rn(2.f, acc[nt][3]));
                if (s < b1r1) { b2r1 = b1r1; i2r1 = i1r1; b1r1 = s; i1r1 = cb + 1; }
                else if (s < b2r1) { b2r1 = s; i2r1 = cb + 1; }
            }
        }

        // ---- exact fp32 rescore of the per-lane top-2 candidates ----
        const float* xr0 = XS + row0 * 65;
        const float* xr1 = XS + row1 * 65;
        float e1 = exact_score(xr0, xsq0, W, WSQ, i1r0);
        float e2 = exact_score(xr0, xsq0, W, WSQ, i2r0);
        float best0; int bi0;
        if (e2 < e1 || (e2 == e1 && i2r0 < i1r0)) { best0 = e2; bi0 = i2r0; }
        else                                      { best0 = e1; bi0 = i1r0; }
        e1 = exact_score(xr1, xsq1, W, WSQ, i1r1);
        e2 = exact_score(xr1, xsq1, W, WSQ, i2r1);
        float best1; int bi1;
        if (e2 < e1 || (e2 == e1 && i2r1 < i1r1)) { best1 = e2; bi1 = i2r1; }
        else                                      { best1 = e1; bi1 = i1r1; }

        // reduce across the 4 lanes sharing a row (tie -> lowest index)
        #pragma unroll
        for (int off = 1; off <= 2; off <<= 1) {
            float sb = __shfl_xor_sync(0xffffffffu, best0, off);
            int   ib = __shfl_xor_sync(0xffffffffu, bi0, off);
            if (sb < best0 || (sb == best0 && ib < bi0)) { best0 = sb; bi0 = ib; }
            sb = __shfl_xor_sync(0xffffffffu, best1, off);
            ib = __shfl_xor_sync(0xffffffffu, bi1, off);
            if (sb < best1 || (sb == best1 && ib < bi1)) { best1 = sb; bi1 = ib; }
        }
        if (t == 0) { IDX[row0] = bi0; IDX[row1] = bi1; }
    }
    __syncthreads();

    // ---- exact gather/loss/denorm (tid < 128) ----
    if (tid < TILE_M) {
        int bi = IDX[tid];
        if (idx_out)
            idx_out[(size_t)blockIdx.x * TILE_M + tid] = (float)bi;
        float mean  = ((float*)(smc + SM_MEAN))[tid];
        float denom = ((float*)(smc + SM_DENOM))[tid];
        const float4* wr = (const float4*)(W + (size_t)bi * DIM);
        float* xr = XS + tid * 65;
        float lsum = 0.f;
        #pragma unroll
        for (int q = 0; q < DIM / 4; q++) {
            float4 b = wr[q];
            float d0 = b.x - xr[4 * q + 0];
            float d1 = b.y - xr[4 * q + 1];
            float d2 = b.z - xr[4 * q + 2];
            float d3 = b.w - xr[4 * q + 3];
            lsum = fmaf(d0, d0, lsum); lsum = fmaf(d1, d1, lsum);
            lsum = fmaf(d2, d2, lsum); lsum = fmaf(d3, d3, lsum);
            xr[4 * q + 0] = fmaf(b.x, denom, mean);
            xr[4 * q + 1] = fmaf(b.y, denom, mean);
            xr[4 * q + 2] = fmaf(b.z, denom, mean);
            xr[4 * q + 3] = fmaf(b.w, denom, mean);
        }
        #pragma unroll
        for (int off = 16; off; off >>= 1)
            lsum = __fadd_rn(lsum, __shfl_down_sync(0xffffffffu, lsum, off));
        if (lid == 0) ((float*)(smc + SM_WACC))[wid] = lsum;
    }
    __syncthreads();

    // ---- coalesced quantized store + block loss ----
    {
        float* og = qout + (size_t)blockIdx.x * (TILE_M * DIM);
        #pragma unroll
        for (int i = tid; i < TILE_M * DIM; i += THREADS)
            og[i] = XS[(i >> 6) * 65 + (i & 63)];
        if (tid == 0) {
            float* wa = (float*)(smc + SM_WACC);
            float s = wa[0];
            #pragma unroll
            for (int w2 = 1; w2 < 4; w2++) s = __fadd_rn(s, wa[w2]);
            g_blockSums[blockIdx.x] = s;
        }
    }
}

__global__ void vq_loss_kernel(float* __restrict__ loss_out) {
    __shared__ float sh[256];
    int t = threadIdx.x;
    float s = 0.f;
    #pragma unroll
    for (int i = 0; i < N_TILES / 256; i++)
        s = __fadd_rn(s, g_blockSums[t + i * 256]);
    sh[t] = s;
    __syncthreads();
    #pragma unroll
    for (int off = 128; off > 0; off >>= 1) {
        if (t < off) sh[t] = __fadd_rn(sh[t], sh[t + off]);
        __syncthreads();
    }
    if (t == 0)
        loss_out[0] = 1.25f * sh[0] * (1.0f / 16777216.0f);
}

extern "C" void kernel_launch(void* const* d_in, const int* in_sizes, int n_in,
                              void* d_out, int out_size)
{
    const float* x = (const float*)d_in[0];
    const float* W = (const float*)d_in[1];
    float* out = (float*)d_out;

    const long long q = (long long)N_ROWS * DIM;  // 16777216
    float* loss_out = nullptr;
    float* idx_out  = nullptr;
    long long osz = (long long)out_size;
    if (osz >= q + 1 + N_ROWS)      { loss_out = out + q; idx_out = out + q + 1; }
    else if (osz == q + N_ROWS)     { idx_out = out + q; }
    else if (osz == q + 1)          { loss_out = out + q; }

    cudaFuncSetAttribute(vq_main, cudaFuncAttributeMaxDynamicSharedMemorySize, SM_TOTAL);
    vq_prep<<<2, 256>>>(W);
    vq_main<<<N_TILES, THREADS, SM_TOTAL>>>(x, W, out, idx_out);
    if (loss_out)
        vq_loss_kernel<<<1, 256>>>(loss_out);
}